// round 9
// baseline (speedup 1.0000x reference)
#include <cuda_runtime.h>

#define NB    8192     // B*N total rows
#define NPTS  4096     // nodes per batch
#define FDIM  64
#define KSEL  21       // k+1 (drop the smallest afterwards)
#define TPB   256      // 8 warps = 8 queries per block

// ---------------- scratch (device globals; no allocation allowed) ----------
__device__ float4 g_pos4[NB];          // (x,y,z,sq)
__device__ float  g_Wh[NB * FDIM];
__device__ float  g_f1[NB];
__device__ float  g_f2[NB];
__device__ float  g_base[NB * FDIM];   // relu(pos@Wp + bp)

__device__ __forceinline__ unsigned int fkey(float f) {
    unsigned int u = __float_as_uint(f);
    return u ^ (0x80000000u | (unsigned int)((int)u >> 31));
}
__device__ __forceinline__ unsigned long long ullmin2(unsigned long long a,
                                                      unsigned long long b) {
    return a < b ? a : b;
}

// ---------------- kernel A: per-node prep (4 rows / 256-thread block) ------
__global__ void __launch_bounds__(256)
prep_kernel(const float* __restrict__ x,
            const float* __restrict__ pos,
            const float* __restrict__ W,
            const float* __restrict__ a,
            const float* __restrict__ Wp,
            const float* __restrict__ bp) {
    int t   = threadIdx.x;
    int r   = t >> 6;            // row slot 0..3
    int j   = t & 63;            // feature 0..63
    int row = blockIdx.x * 4 + r;
    __shared__ float xs[4][FDIM];
    __shared__ float red[4][4];

    xs[r][j] = x[row * FDIM + j];
    __syncthreads();

    float acc = 0.f;
#pragma unroll 16
    for (int i = 0; i < FDIM; i++)
        acc += xs[r][i] * W[i * FDIM + j];
    g_Wh[row * FDIM + j] = acc;

    float p1 = acc * a[j];
    float p2 = acc * a[FDIM + j];
#pragma unroll
    for (int off = 16; off; off >>= 1) {
        p1 += __shfl_down_sync(0xffffffffu, p1, off);
        p2 += __shfl_down_sync(0xffffffffu, p2, off);
    }
    int lane = j & 31, half = j >> 5;
    if (lane == 0) { red[r][half] = p1; red[r][2 + half] = p2; }

    float px = pos[row * 3 + 0];
    float py = pos[row * 3 + 1];
    float pz = pos[row * 3 + 2];
    float bj = px * Wp[j] + py * Wp[FDIM + j] + pz * Wp[2 * FDIM + j] + bp[j];
    g_base[row * FDIM + j] = bj > 0.f ? bj : 0.f;

    __syncthreads();
    if (j == 0) {
        g_f1[row] = red[r][0] + red[r][1];
        g_f2[row] = red[r][2] + red[r][3];
        float sq  = px * px + py * py + pz * pz;
        g_pos4[row] = make_float4(px, py, pz, sq);
    }
}

// branchless stable float-key insert level
#define INS_LEVF(kk, ii, ck, ci)                          \
    {                                                     \
        bool c = ck < kk;                                 \
        float nk = c ? ck : kk;                           \
        unsigned int ni = c ? ci : ii;                    \
        ck = c ? kk : ck;  ci = c ? ii : ci;              \
        kk = nk;  ii = ni;                                \
    }
// branchless stable u32-key insert level (refill rescan)
#define INS_LEVU(kk, ii, ck, ci)                          \
    {                                                     \
        bool c = ck < kk;                                 \
        unsigned int nk = c ? ck : kk, ni = c ? ci : ii;  \
        ck = c ? kk : ck;  ci = c ? ii : ci;              \
        kk = nk;  ii = ni;                                \
    }
#define CE64(lo, hi)                                      \
    {                                                     \
        unsigned long long mn = lo < hi ? lo : hi;        \
        hi = lo < hi ? hi : lo;                           \
        lo = mn;                                          \
    }
// top-4 union of two sorted-4 u64 lists (bitonic half-clean + sort4)
#define UNION4(o0, o1, o2, o3, x0, x1, x2, x3, y0, y1, y2, y3)  \
    {                                                           \
        o0 = ullmin2(x0, y3); o1 = ullmin2(x1, y2);             \
        o2 = ullmin2(x2, y1); o3 = ullmin2(x3, y0);             \
        CE64(o0, o2) CE64(o1, o3) CE64(o0, o1) CE64(o2, o3)     \
    }

// ---------------- kernel B: warp-per-query kNN(21) + attention -------------
// Lane owns 128 candidates (m = lane + 32*i) as FOUR independent cascade
// streams for ILP. No shared memory, no block barriers.
__global__ void __launch_bounds__(TPB)
knn_attn_kernel(float* __restrict__ out) {
    const unsigned FULL = 0xffffffffu;
    int lane = threadIdx.x & 31;
    int wid  = threadIdx.x >> 5;
    int row  = blockIdx.x * (TPB / 32) + wid;      // this warp's query
    int browbase = (row >> 12) << 12;              // first row of batch
    const float4* pb = g_pos4 + browbase;

    float4 q = g_pos4[row];

    // ---- phase 1: four independent branchless top-4 cascades --------------
    const float INF = __int_as_float(0x7f800000);
    float ak0 = INF, ak1 = INF, ak2 = INF, ak3 = INF;
    float bk0 = INF, bk1 = INF, bk2 = INF, bk3 = INF;
    float ck0 = INF, ck1 = INF, ck2 = INF, ck3 = INF;
    float dk0 = INF, dk1 = INF, dk2 = INF, dk3 = INF;
    unsigned int ai0 = 0xFFFu, ai1 = 0xFFFu, ai2 = 0xFFFu, ai3 = 0xFFFu;
    unsigned int bi0 = 0xFFFu, bi1 = 0xFFFu, bi2 = 0xFFFu, bi3 = 0xFFFu;
    unsigned int ci0 = 0xFFFu, ci1 = 0xFFFu, ci2 = 0xFFFu, ci3 = 0xFFFu;
    unsigned int di0 = 0xFFFu, di1 = 0xFFFu, di2 = 0xFFFu, di3 = 0xFFFu;
#pragma unroll 2
    for (int i = 0; i < 32; i++) {
        int mA = lane + 32 * i;
        int mB = mA + 32 * 32;
        int mC = mA + 64 * 32;
        int mD = mA + 96 * 32;
        float4 pA = pb[mA];
        float4 pB = pb[mB];
        float4 pC = pb[mC];
        float4 pD = pb[mD];

        float dA = fmaf(-2.f, fmaf(q.z, pA.z, fmaf(q.y, pA.y, q.x * pA.x)),
                        q.w + pA.w);
        float dB = fmaf(-2.f, fmaf(q.z, pB.z, fmaf(q.y, pB.y, q.x * pB.x)),
                        q.w + pB.w);
        float dC = fmaf(-2.f, fmaf(q.z, pC.z, fmaf(q.y, pC.y, q.x * pC.x)),
                        q.w + pC.w);
        float dD = fmaf(-2.f, fmaf(q.z, pD.z, fmaf(q.y, pD.y, q.x * pD.x)),
                        q.w + pD.w);

        unsigned int xiA = (unsigned int)mA;
        INS_LEVF(ak0, ai0, dA, xiA)
        INS_LEVF(ak1, ai1, dA, xiA)
        INS_LEVF(ak2, ai2, dA, xiA)
        INS_LEVF(ak3, ai3, dA, xiA)

        unsigned int xiB = (unsigned int)mB;
        INS_LEVF(bk0, bi0, dB, xiB)
        INS_LEVF(bk1, bi1, dB, xiB)
        INS_LEVF(bk2, bi2, dB, xiB)
        INS_LEVF(bk3, bi3, dB, xiB)

        unsigned int xiC = (unsigned int)mC;
        INS_LEVF(ck0, ci0, dC, xiC)
        INS_LEVF(ck1, ci1, dC, xiC)
        INS_LEVF(ck2, ci2, dC, xiC)
        INS_LEVF(ck3, ci3, dC, xiC)

        unsigned int xiD = (unsigned int)mD;
        INS_LEVF(dk0, di0, dD, xiD)
        INS_LEVF(dk1, di1, dD, xiD)
        INS_LEVF(dk2, di2, dD, xiD)
        INS_LEVF(dk3, di3, dD, xiD)
    }

    // ---- union-merge the four sorted 4-lists -> exact sorted top-4 --------
    unsigned long long l1, l2, l3, bound;
    unsigned int hk, hidx, hflag;
    {
        unsigned long long A0 = (((unsigned long long)fkey(ak0)) << 13) | ai0;
        unsigned long long A1 = (((unsigned long long)fkey(ak1)) << 13) | ai1;
        unsigned long long A2 = (((unsigned long long)fkey(ak2)) << 13) | ai2;
        unsigned long long A3 = (((unsigned long long)fkey(ak3)) << 13) | ai3;
        unsigned long long B0 = (((unsigned long long)fkey(bk0)) << 13) | bi0;
        unsigned long long B1 = (((unsigned long long)fkey(bk1)) << 13) | bi1;
        unsigned long long B2 = (((unsigned long long)fkey(bk2)) << 13) | bi2;
        unsigned long long B3 = (((unsigned long long)fkey(bk3)) << 13) | bi3;
        unsigned long long C0 = (((unsigned long long)fkey(ck0)) << 13) | ci0;
        unsigned long long C1 = (((unsigned long long)fkey(ck1)) << 13) | ci1;
        unsigned long long C2 = (((unsigned long long)fkey(ck2)) << 13) | ci2;
        unsigned long long C3 = (((unsigned long long)fkey(ck3)) << 13) | ci3;
        unsigned long long D0 = (((unsigned long long)fkey(dk0)) << 13) | di0;
        unsigned long long D1 = (((unsigned long long)fkey(dk1)) << 13) | di1;
        unsigned long long D2 = (((unsigned long long)fkey(dk2)) << 13) | di2;
        unsigned long long D3 = (((unsigned long long)fkey(dk3)) << 13) | di3;
        unsigned long long U0, U1, U2, U3, V0, V1, V2, V3;
        UNION4(U0, U1, U2, U3, A0, A1, A2, A3, B0, B1, B2, B3)
        UNION4(V0, V1, V2, V3, C0, C1, C2, C3, D0, D1, D2, D3)
        unsigned long long c0, c1, c2, c3;
        UNION4(c0, c1, c2, c3, U0, U1, U2, U3, V0, V1, V2, V3)
        hk    = (unsigned int)(c0 >> 13);
        hidx  = (unsigned int)c0 & 0xFFFu;
        hflag = 0;
        l1 = c1; l2 = c2; l3 = c3;
        bound = c3 | 0x1000ull;    // sentinel: flagged copy of last exact elem
    }

    // ---- 21 merge rounds; sentinel win -> incremental single-lane refill --
    unsigned int nbr = 0;
    int hp = 1;
    int r  = 0;
    while (r < KSEL) {
        unsigned int w = __reduce_min_sync(FULL, hk);
        unsigned int cand = (hk == w) ? hidx : 0xFFFFu;
        unsigned int m = __reduce_min_sync(FULL, cand);
        bool mine = (hk == w) && (hidx == m);
        if (__ballot_sync(FULL, mine && hflag)) {
            // exhausted lane refills: top-4 of its candidates with packed
            // key strictly greater than the sentinel (== last consumed elem)
            if (mine && hflag) {
                unsigned long long fcut =
                    (((unsigned long long)hk) << 13) | hidx;
                unsigned int k0 = ~0u, k1 = ~0u, k2 = ~0u, k3 = ~0u;
                unsigned int i0 = 0xFFFu, i1 = 0xFFFu, i2 = 0xFFFu,
                             i3 = 0xFFFu;
#pragma unroll 1
                for (int i = 0; i < 128; i++) {
                    int mm = lane + 32 * i;
                    float4 p = pb[mm];
                    float dot = fmaf(q.z, p.z, fmaf(q.y, p.y, q.x * p.x));
                    float d2  = fmaf(-2.f, dot, q.w + p.w);
                    unsigned int key = fkey(d2);
                    unsigned long long pk =
                        (((unsigned long long)key) << 13) | (unsigned int)mm;
                    bool ok = pk > fcut;
                    unsigned int cku = ok ? key : 0xFFFFFFFFu;
                    unsigned int ciu = ok ? (unsigned int)mm : 0xFFFu;
                    INS_LEVU(k0, i0, cku, ciu)
                    INS_LEVU(k1, i1, cku, ciu)
                    INS_LEVU(k2, i2, cku, ciu)
                    INS_LEVU(k3, i3, cku, ciu)
                }
                hk = k0; hidx = i0; hflag = 0;
                l1 = (((unsigned long long)k1) << 13) | i1;
                l2 = (((unsigned long long)k2) << 13) | i2;
                l3 = (((unsigned long long)k3) << 13) | i3;
                bound = l3 | 0x1000ull;
                hp = 1;
            }
            continue;                    // retry this round
        }
        if (lane == r - 1) nbr = m;      // rounds 1..20 record neighbors
        if (mine) {
            unsigned long long v = (hp == 1) ? l1 : (hp == 2) ? l2
                                 : (hp == 3) ? l3 : bound;
            hp++;
            hk    = (unsigned int)(v >> 13);
            hidx  = (unsigned int)v & 0xFFFu;
            hflag = (unsigned int)(v >> 12) & 1u;
        }
        r++;
    }

    // ---- softmax over the 20 neighbors (in-warp) --------------------------
    float e = -1e30f;
    if (lane < KSEL - 1) {
        float val = g_f1[row] + g_f2[browbase + (int)nbr];
        e = val > 0.f ? val : 0.2f * val;            // leaky relu 0.2
    }
    float mx = e;
#pragma unroll
    for (int off = 16; off; off >>= 1)
        mx = fmaxf(mx, __shfl_xor_sync(FULL, mx, off));
    float ex = (lane < KSEL - 1) ? expf(e - mx) : 0.f;
    float sm = ex;
#pragma unroll
    for (int off = 16; off; off >>= 1)
        sm += __shfl_xor_sync(FULL, sm, off);
    float attn = ex / sm;                            // valid on lanes < 20

    // ---- weighted Wh gather + base + elu (2 features per lane) ------------
    float acc0 = g_base[row * FDIM + lane];
    float acc1 = g_base[row * FDIM + 32 + lane];
#pragma unroll
    for (int j = 0; j < KSEL - 1; j++) {
        int   mj = (int)__shfl_sync(FULL, nbr, j);
        float aj = __shfl_sync(FULL, attn, j);
        const float* wr = g_Wh + (browbase + mj) * FDIM;
        acc0 = fmaf(aj, wr[lane],      acc0);
        acc1 = fmaf(aj, wr[32 + lane], acc1);
    }
    out[row * FDIM + lane]      = acc0 > 0.f ? acc0 : expm1f(acc0);
    out[row * FDIM + 32 + lane] = acc1 > 0.f ? acc1 : expm1f(acc1);
}

// ---------------- launch ----------------------------------------------------
extern "C" void kernel_launch(void* const* d_in, const int* in_sizes, int n_in,
                              void* d_out, int out_size) {
    (void)in_sizes; (void)n_in; (void)out_size;
    const float* x   = (const float*)d_in[0];
    const float* pos = (const float*)d_in[1];
    const float* W   = (const float*)d_in[2];
    const float* a   = (const float*)d_in[3];
    const float* Wp  = (const float*)d_in[4];
    const float* bp  = (const float*)d_in[5];
    float* out = (float*)d_out;

    prep_kernel<<<NB / 4, 256>>>(x, pos, W, a, Wp, bp);
    knn_attn_kernel<<<NB / (TPB / 32), TPB>>>(out);
}

// round 10
// speedup vs baseline: 1.3077x; 1.3077x over previous
#include <cuda_runtime.h>

#define NB    8192     // B*N total rows
#define NPTS  4096     // nodes per batch
#define FDIM  64
#define KSEL  21       // k+1 (drop the smallest afterwards)
#define TPB   128      // 4 warps = 4 queries per block

// ---------------- scratch (device globals; no allocation allowed) ----------
__device__ float4 g_pos4[NB];          // (x,y,z,sq)
__device__ float  g_Wh[NB * FDIM];
__device__ float  g_f1[NB];
__device__ float  g_f2[NB];
__device__ float  g_base[NB * FDIM];   // relu(pos@Wp + bp)

__device__ __forceinline__ unsigned int fkey(float f) {
    unsigned int u = __float_as_uint(f);
    return u ^ (0x80000000u | (unsigned int)((int)u >> 31));
}
__device__ __forceinline__ unsigned long long ullmin2(unsigned long long a,
                                                      unsigned long long b) {
    return a < b ? a : b;
}

// ---------------- kernel A: per-node prep (4 rows / 256-thread block) ------
__global__ void __launch_bounds__(256)
prep_kernel(const float* __restrict__ x,
            const float* __restrict__ pos,
            const float* __restrict__ W,
            const float* __restrict__ a,
            const float* __restrict__ Wp,
            const float* __restrict__ bp) {
    int t   = threadIdx.x;
    int r   = t >> 6;            // row slot 0..3
    int j   = t & 63;            // feature 0..63
    int row = blockIdx.x * 4 + r;
    __shared__ float xs[4][FDIM];
    __shared__ float red[4][4];

    xs[r][j] = x[row * FDIM + j];
    __syncthreads();

    float acc = 0.f;
#pragma unroll 16
    for (int i = 0; i < FDIM; i++)
        acc += xs[r][i] * W[i * FDIM + j];
    g_Wh[row * FDIM + j] = acc;

    float p1 = acc * a[j];
    float p2 = acc * a[FDIM + j];
#pragma unroll
    for (int off = 16; off; off >>= 1) {
        p1 += __shfl_down_sync(0xffffffffu, p1, off);
        p2 += __shfl_down_sync(0xffffffffu, p2, off);
    }
    int lane = j & 31, half = j >> 5;
    if (lane == 0) { red[r][half] = p1; red[r][2 + half] = p2; }

    float px = pos[row * 3 + 0];
    float py = pos[row * 3 + 1];
    float pz = pos[row * 3 + 2];
    float bj = px * Wp[j] + py * Wp[FDIM + j] + pz * Wp[2 * FDIM + j] + bp[j];
    g_base[row * FDIM + j] = bj > 0.f ? bj : 0.f;

    __syncthreads();
    if (j == 0) {
        g_f1[row] = red[r][0] + red[r][1];
        g_f2[row] = red[r][2] + red[r][3];
        float sq  = px * px + py * py + pz * pz;
        g_pos4[row] = make_float4(px, py, pz, sq);
    }
}

// branchless stable float-key insert level
#define INS_LEVF(kk, ii, ck, ci)                          \
    {                                                     \
        bool c = ck < kk;                                 \
        float nk = c ? ck : kk;                           \
        unsigned int ni = c ? ci : ii;                    \
        ck = c ? kk : ck;  ci = c ? ii : ci;              \
        kk = nk;  ii = ni;                                \
    }
// branchless stable u32-key insert level (refill rescan)
#define INS_LEVU(kk, ii, ck, ci)                          \
    {                                                     \
        bool c = ck < kk;                                 \
        unsigned int nk = c ? ck : kk, ni = c ? ci : ii;  \
        ck = c ? kk : ck;  ci = c ? ii : ci;              \
        kk = nk;  ii = ni;                                \
    }

// packed element: key<<13 | idx<<1 | flag  (flag=1 only on sentinels)
__device__ __forceinline__ unsigned long long pack_e(unsigned int key,
                                                     unsigned int idx) {
    return (((unsigned long long)key) << 13) | (idx << 1);
}

// ---------------- kernel B: warp-per-query kNN(21) + attention -------------
// Lane owns two streams of 64 candidates (m = lane+32i, i<64 / i>=64), each
// kept as exact sorted top-3 (with idx) + 4th key as sentinel bound.
__global__ void __launch_bounds__(TPB)
knn_attn_kernel(float* __restrict__ out) {
    const unsigned FULL = 0xffffffffu;
    int lane = threadIdx.x & 31;
    int wid  = threadIdx.x >> 5;
    int row  = blockIdx.x * (TPB / 32) + wid;      // this warp's query
    int browbase = (row >> 12) << 12;              // first row of batch
    const float4* pb = g_pos4 + browbase;

    float4 q = g_pos4[row];

    // ---- phase 1: two streams, top-3 (+4th-key bound) each ----------------
    const float INF = __int_as_float(0x7f800000);
    float fa0 = INF, fa1 = INF, fa2 = INF, fa3 = INF;
    float fb0 = INF, fb1 = INF, fb2 = INF, fb3 = INF;
    unsigned int ia0 = 0xFFFu, ia1 = 0xFFFu, ia2 = 0xFFFu;
    unsigned int ib0 = 0xFFFu, ib1 = 0xFFFu, ib2 = 0xFFFu;
#pragma unroll 4
    for (int i = 0; i < 64; i++) {
        int mA = lane + 32 * i;
        int mB = mA + 2048;
        float4 pA = pb[mA];
        float4 pB = pb[mB];

        float dA = fmaf(-2.f, fmaf(q.z, pA.z, fmaf(q.y, pA.y, q.x * pA.x)),
                        q.w + pA.w);
        unsigned int xiA = (unsigned int)mA;
        INS_LEVF(fa0, ia0, dA, xiA)
        INS_LEVF(fa1, ia1, dA, xiA)
        INS_LEVF(fa2, ia2, dA, xiA)
        fa3 = fminf(fa3, dA);                      // 4th-smallest key bound

        float dB = fmaf(-2.f, fmaf(q.z, pB.z, fmaf(q.y, pB.y, q.x * pB.x)),
                        q.w + pB.w);
        unsigned int xiB = (unsigned int)mB;
        INS_LEVF(fb0, ib0, dB, xiB)
        INS_LEVF(fb1, ib1, dB, xiB)
        INS_LEVF(fb2, ib2, dB, xiB)
        fb3 = fminf(fb3, dB);
    }

    // ---- pack lists; sentinel = 4th key, idx 0, flag bit0 -----------------
    unsigned long long LA1 = pack_e(fkey(fa1), ia1);
    unsigned long long LA2 = pack_e(fkey(fa2), ia2);
    unsigned long long LB1 = pack_e(fkey(fb1), ib1);
    unsigned long long LB2 = pack_e(fkey(fb2), ib2);
    unsigned long long sentA = (((unsigned long long)fkey(fa3)) << 13) | 1ull;
    unsigned long long sentB = (((unsigned long long)fkey(fb3)) << 13) | 1ull;
    unsigned long long headA = pack_e(fkey(fa0), ia0);
    unsigned long long headB = pack_e(fkey(fb0), ib0);
    int apos = 0, bpos = 0;

    // ---- 21 merge rounds; sentinel win -> single-lane stream refill -------
    unsigned int nbr = 0;
    int r = 0;
    while (r < KSEL) {
        unsigned long long h = ullmin2(headA, headB);
        unsigned int hk = (unsigned int)(h >> 13);
        unsigned int w  = __reduce_min_sync(FULL, hk);
        unsigned int cand = (hk == w) ? ((unsigned int)(h >> 1) & 0xFFFu)
                                      : 0xFFFFu;
        unsigned int m = __reduce_min_sync(FULL, cand);
        bool mine = (hk == w) && (((unsigned int)(h >> 1) & 0xFFFu) == m);
        bool sfire = mine && ((unsigned int)h & 1u);
        if (__ballot_sync(FULL, sfire)) {
            if (sfire) {
                // refill the stream whose sentinel fired: top-3 of its
                // candidates with packed key strictly greater than cut
                bool fromA = (h == headA);
                unsigned long long cut = fromA ? LA2 : LB2;
                int mbase = fromA ? 0 : 2048;
                unsigned int k0 = ~0u, k1 = ~0u, k2 = ~0u, k3 = ~0u;
                unsigned int i0 = 0xFFFu, i1 = 0xFFFu, i2 = 0xFFFu;
#pragma unroll 1
                for (int i = 0; i < 64; i++) {
                    int mm = lane + 32 * i + mbase;
                    float4 p = pb[mm];
                    float dot = fmaf(q.z, p.z, fmaf(q.y, p.y, q.x * p.x));
                    float d2  = fmaf(-2.f, dot, q.w + p.w);
                    unsigned int key = fkey(d2);
                    bool ok = pack_e(key, (unsigned int)mm) > cut;
                    unsigned int ck = ok ? key : 0xFFFFFFFFu;
                    unsigned int ci = ok ? (unsigned int)mm : 0xFFFu;
                    INS_LEVU(k0, i0, ck, ci)
                    INS_LEVU(k1, i1, ck, ci)
                    INS_LEVU(k2, i2, ck, ci)
                    k3 = min(k3, ck);
                }
                unsigned long long nh = pack_e(k0, i0);
                unsigned long long n1 = pack_e(k1, i1);
                unsigned long long n2 = pack_e(k2, i2);
                unsigned long long ns = (((unsigned long long)k3) << 13) | 1ull;
                if (fromA) { headA = nh; LA1 = n1; LA2 = n2; sentA = ns;
                             apos = 0; }
                else       { headB = nh; LB1 = n1; LB2 = n2; sentB = ns;
                             bpos = 0; }
            }
            continue;                    // retry this round
        }
        if (lane == r - 1) nbr = m;      // rounds 1..20 record neighbors
        if (mine) {
            if (h == headA) {
                apos++;
                headA = (apos == 1) ? LA1 : (apos == 2) ? LA2 : sentA;
            } else {
                bpos++;
                headB = (bpos == 1) ? LB1 : (bpos == 2) ? LB2 : sentB;
            }
        }
        r++;
    }

    // ---- softmax over the 20 neighbors (in-warp) --------------------------
    float e = -1e30f;
    if (lane < KSEL - 1) {
        float val = g_f1[row] + g_f2[browbase + (int)nbr];
        e = val > 0.f ? val : 0.2f * val;            // leaky relu 0.2
    }
    float mx = e;
#pragma unroll
    for (int off = 16; off; off >>= 1)
        mx = fmaxf(mx, __shfl_xor_sync(FULL, mx, off));
    float ex = (lane < KSEL - 1) ? expf(e - mx) : 0.f;
    float sm = ex;
#pragma unroll
    for (int off = 16; off; off >>= 1)
        sm += __shfl_xor_sync(FULL, sm, off);
    float attn = ex / sm;                            // valid on lanes < 20

    // ---- weighted Wh gather + base + elu (2 features per lane) ------------
    float acc0 = g_base[row * FDIM + lane];
    float acc1 = g_base[row * FDIM + 32 + lane];
#pragma unroll
    for (int j = 0; j < KSEL - 1; j++) {
        int   mj = (int)__shfl_sync(FULL, nbr, j);
        float aj = __shfl_sync(FULL, attn, j);
        const float* wr = g_Wh + (browbase + mj) * FDIM;
        acc0 = fmaf(aj, wr[lane],      acc0);
        acc1 = fmaf(aj, wr[32 + lane], acc1);
    }
    out[row * FDIM + lane]      = acc0 > 0.f ? acc0 : expm1f(acc0);
    out[row * FDIM + 32 + lane] = acc1 > 0.f ? acc1 : expm1f(acc1);
}

// ---------------- launch ----------------------------------------------------
extern "C" void kernel_launch(void* const* d_in, const int* in_sizes, int n_in,
                              void* d_out, int out_size) {
    (void)in_sizes; (void)n_in; (void)out_size;
    const float* x   = (const float*)d_in[0];
    const float* pos = (const float*)d_in[1];
    const float* W   = (const float*)d_in[2];
    const float* a   = (const float*)d_in[3];
    const float* Wp  = (const float*)d_in[4];
    const float* bp  = (const float*)d_in[5];
    float* out = (float*)d_out;

    prep_kernel<<<NB / 4, 256>>>(x, pos, W, a, Wp, bp);
    knn_attn_kernel<<<NB / (TPB / 32), TPB>>>(out);
}

// round 13
// speedup vs baseline: 1.3249x; 1.0132x over previous
#include <cuda_runtime.h>

#define NB    8192     // B*N total rows
#define NPTS  4096     // nodes per batch
#define FDIM  64
#define KSEL  21       // k+1 (drop the smallest afterwards)
#define TPB   128      // 4 warps = 4 queries per block

// ---------------- scratch (device globals; no allocation allowed) ----------
__device__ float4 g_pos4[NB];          // (x,y,z,sq)
__device__ float2 g_Whp[NB * 32];      // packed: [row][lane] = (Wh[l], Wh[l+32])
__device__ float  g_f1[NB];
__device__ float  g_f2[NB];
__device__ float  g_base[NB * FDIM];   // relu(pos@Wp + bp)

__device__ __forceinline__ unsigned int fkey(float f) {
    unsigned int u = __float_as_uint(f);
    return u ^ (0x80000000u | (unsigned int)((int)u >> 31));
}
__device__ __forceinline__ unsigned long long ullmin2(unsigned long long a,
                                                      unsigned long long b) {
    return a < b ? a : b;
}

// ---------------- kernel A: per-node prep (4 rows / 256-thread block) ------
__global__ void __launch_bounds__(256)
prep_kernel(const float* __restrict__ x,
            const float* __restrict__ pos,
            const float* __restrict__ W,
            const float* __restrict__ a,
            const float* __restrict__ Wp,
            const float* __restrict__ bp) {
    int t   = threadIdx.x;
    int r   = t >> 6;            // row slot 0..3
    int j   = t & 63;            // feature 0..63
    int row = blockIdx.x * 4 + r;
    __shared__ float xs[4][FDIM];
    __shared__ float red[4][4];

    xs[r][j] = x[row * FDIM + j];
    __syncthreads();

    float acc = 0.f;
#pragma unroll 16
    for (int i = 0; i < FDIM; i++)
        acc += xs[r][i] * W[i * FDIM + j];
    // packed Wh: float2 element (Wh[j&31].x for j<32, .y for j>=32)
    {
        float* wp = (float*)&g_Whp[row * 32 + (j & 31)];
        wp[j >> 5] = acc;
    }

    float p1 = acc * a[j];
    float p2 = acc * a[FDIM + j];
#pragma unroll
    for (int off = 16; off; off >>= 1) {
        p1 += __shfl_down_sync(0xffffffffu, p1, off);
        p2 += __shfl_down_sync(0xffffffffu, p2, off);
    }
    int lane = j & 31, half = j >> 5;
    if (lane == 0) { red[r][half] = p1; red[r][2 + half] = p2; }

    float px = pos[row * 3 + 0];
    float py = pos[row * 3 + 1];
    float pz = pos[row * 3 + 2];
    float bj = px * Wp[j] + py * Wp[FDIM + j] + pz * Wp[2 * FDIM + j] + bp[j];
    g_base[row * FDIM + j] = bj > 0.f ? bj : 0.f;

    __syncthreads();
    if (j == 0) {
        g_f1[row] = red[r][0] + red[r][1];
        g_f2[row] = red[r][2] + red[r][3];
        float sq  = px * px + py * py + pz * pz;
        g_pos4[row] = make_float4(px, py, pz, sq);
    }
}

// branchless stable float-key insert level (ck/ci become the ejected value)
#define INS_LEVF(kk, ii, ck, ci)                          \
    {                                                     \
        bool c = ck < kk;                                 \
        float nk = c ? ck : kk;                           \
        unsigned int ni = c ? ci : ii;                    \
        ck = c ? kk : ck;  ci = c ? ii : ci;              \
        kk = nk;  ii = ni;                                \
    }
// branchless stable u32-key insert level (refill rescan)
#define INS_LEVU(kk, ii, ck, ci)                          \
    {                                                     \
        bool c = ck < kk;                                 \
        unsigned int nk = c ? ck : kk, ni = c ? ci : ii;  \
        ck = c ? kk : ck;  ci = c ? ii : ci;              \
        kk = nk;  ii = ni;                                \
    }

// packed element: key<<13 | idx<<1 | flag  (flag=1 only on sentinels)
__device__ __forceinline__ unsigned long long pack_e(unsigned int key,
                                                     unsigned int idx) {
    return (((unsigned long long)key) << 13) | (idx << 1);
}

// ---------------- kernel B: warp-per-query kNN(21) + attention -------------
// Lane owns two streams of 64 candidates (m = lane+32i, i<64 / i>=64), each
// kept as exact sorted top-2 (with idx) + exact 3rd-key sentinel bound.
__global__ void __launch_bounds__(TPB)
knn_attn_kernel(float* __restrict__ out) {
    const unsigned FULL = 0xffffffffu;
    int lane = threadIdx.x & 31;
    int wid  = threadIdx.x >> 5;
    int row  = blockIdx.x * (TPB / 32) + wid;      // this warp's query
    int browbase = (row >> 12) << 12;              // first row of batch
    const float4* pb = g_pos4 + browbase;

    float4 q = g_pos4[row];

    // ---- phase 1: two streams, top-2 (+3rd-key bound) each ----------------
    const float INF = __int_as_float(0x7f800000);
    float fa0 = INF, fa1 = INF, fa2 = INF;
    float fb0 = INF, fb1 = INF, fb2 = INF;
    unsigned int ia0 = 0xFFFu, ia1 = 0xFFFu;
    unsigned int ib0 = 0xFFFu, ib1 = 0xFFFu;
#pragma unroll 4
    for (int i = 0; i < 64; i++) {
        int mA = lane + 32 * i;
        int mB = mA + 2048;
        float4 pA = pb[mA];
        float4 pB = pb[mB];

        float dA = fmaf(-2.f, fmaf(q.z, pA.z, fmaf(q.y, pA.y, q.x * pA.x)),
                        q.w + pA.w);
        unsigned int xiA = (unsigned int)mA;
        INS_LEVF(fa0, ia0, dA, xiA)
        INS_LEVF(fa1, ia1, dA, xiA)
        fa2 = fminf(fa2, dA);                      // dA now = ejected value

        float dB = fmaf(-2.f, fmaf(q.z, pB.z, fmaf(q.y, pB.y, q.x * pB.x)),
                        q.w + pB.w);
        unsigned int xiB = (unsigned int)mB;
        INS_LEVF(fb0, ib0, dB, xiB)
        INS_LEVF(fb1, ib1, dB, xiB)
        fb2 = fminf(fb2, dB);
    }

    // ---- pack lists; sentinel = exact 3rd key, idx-bits 0, flag bit0 ------
    unsigned long long LA1 = pack_e(fkey(fa1), ia1);
    unsigned long long LB1 = pack_e(fkey(fb1), ib1);
    unsigned long long sentA = (((unsigned long long)fkey(fa2)) << 13) | 1ull;
    unsigned long long sentB = (((unsigned long long)fkey(fb2)) << 13) | 1ull;
    unsigned long long headA = pack_e(fkey(fa0), ia0);
    unsigned long long headB = pack_e(fkey(fb0), ib0);
    int apos = 0, bpos = 0;

    // ---- 21 merge rounds; sentinel win -> single-lane stream refill -------
    unsigned int nbr = 0;
    int r = 0;
    while (r < KSEL) {
        unsigned long long h = ullmin2(headA, headB);
        unsigned int hk = (unsigned int)(h >> 13);
        unsigned int w  = __reduce_min_sync(FULL, hk);
        unsigned int cand = (hk == w) ? ((unsigned int)(h >> 1) & 0xFFFu)
                                      : 0xFFFFu;
        unsigned int m = __reduce_min_sync(FULL, cand);
        bool mine = (hk == w) && (((unsigned int)(h >> 1) & 0xFFFu) == m);
        bool sfire = mine && ((unsigned int)h & 1u);
        if (__ballot_sync(FULL, sfire)) {
            if (sfire) {
                // refill the stream whose sentinel fired: top-2 + 3rd-key
                // bound among candidates with packed key strictly > cut
                bool fromA = (h == headA);
                unsigned long long cut = fromA ? LA1 : LB1;
                int mbase = fromA ? 0 : 2048;
                unsigned int k0 = ~0u, k1 = ~0u, k2 = ~0u;
                unsigned int i0 = 0xFFFu, i1 = 0xFFFu;
#pragma unroll 1
                for (int i = 0; i < 64; i++) {
                    int mm = lane + 32 * i + mbase;
                    float4 p = pb[mm];
                    float dot = fmaf(q.z, p.z, fmaf(q.y, p.y, q.x * p.x));
                    float d2  = fmaf(-2.f, dot, q.w + p.w);
                    unsigned int key = fkey(d2);
                    bool ok = pack_e(key, (unsigned int)mm) > cut;
                    unsigned int ck = ok ? key : 0xFFFFFFFFu;
                    unsigned int ci = ok ? (unsigned int)mm : 0xFFFu;
                    INS_LEVU(k0, i0, ck, ci)
                    INS_LEVU(k1, i1, ck, ci)
                    k2 = min(k2, ck);              // ck = ejected value
                }
                unsigned long long nh = pack_e(k0, i0);
                unsigned long long n1 = pack_e(k1, i1);
                unsigned long long ns = (((unsigned long long)k2) << 13) | 1ull;
                if (fromA) { headA = nh; LA1 = n1; sentA = ns; apos = 0; }
                else       { headB = nh; LB1 = n1; sentB = ns; bpos = 0; }
            }
            continue;                    // retry this round
        }
        if (lane == r - 1) nbr = m;      // rounds 1..20 record neighbors
        if (mine) {
            if (h == headA) {
                apos++;
                headA = (apos == 1) ? LA1 : sentA;
            } else {
                bpos++;
                headB = (bpos == 1) ? LB1 : sentB;
            }
        }
        r++;
    }

    // ---- softmax over the 20 neighbors (in-warp) --------------------------
    float e = -1e30f;
    if (lane < KSEL - 1) {
        float val = g_f1[row] + g_f2[browbase + (int)nbr];
        e = val > 0.f ? val : 0.2f * val;            // leaky relu 0.2
    }
    float mx = e;
#pragma unroll
    for (int off = 16; off; off >>= 1)
        mx = fmaxf(mx, __shfl_xor_sync(FULL, mx, off));
    float ex = (lane < KSEL - 1) ? expf(e - mx) : 0.f;
    float sm = ex;
#pragma unroll
    for (int off = 16; off; off >>= 1)
        sm += __shfl_xor_sync(FULL, sm, off);
    float attn = ex / sm;                            // valid on lanes < 20

    // ---- weighted Wh gather + base + elu (2 features per lane) ------------
    float acc0 = g_base[row * FDIM + lane];
    float acc1 = g_base[row * FDIM + 32 + lane];
#pragma unroll
    for (int j = 0; j < KSEL - 1; j++) {
        int   mj = (int)__shfl_sync(FULL, nbr, j);
        float aj = __shfl_sync(FULL, attn, j);
        float2 wv = g_Whp[(browbase + mj) * 32 + lane];
        acc0 = fmaf(aj, wv.x, acc0);
        acc1 = fmaf(aj, wv.y, acc1);
    }
    out[row * FDIM + lane]      = acc0 > 0.f ? acc0 : expm1f(acc0);
    out[row * FDIM + 32 + lane] = acc1 > 0.f ? acc1 : expm1f(acc1);
}

// ---------------- launch ----------------------------------------------------
extern "C" void kernel_launch(void* const* d_in, const int* in_sizes, int n_in,
                              void* d_out, int out_size) {
    (void)in_sizes; (void)n_in; (void)out_size;
    const float* x   = (const float*)d_in[0];
    const float* pos = (const float*)d_in[1];
    const float* W   = (const float*)d_in[2];
    const float* a   = (const float*)d_in[3];
    const float* Wp  = (const float*)d_in[4];
    const float* bp  = (const float*)d_in[5];
    float* out = (float*)d_out;

    prep_kernel<<<NB / 4, 256>>>(x, pos, W, a, Wp, bp);
    knn_attn_kernel<<<NB / (TPB / 32), TPB>>>(out);
}

// round 15
// speedup vs baseline: 1.3930x; 1.0514x over previous
#include <cuda_runtime.h>

#define NB    8192     // B*N total rows
#define NPTS  4096     // nodes per batch
#define FDIM  64
#define KSEL  21       // k+1 (drop the smallest afterwards)
#define TPB   128      // 4 warps = 4 queries per block

// ---------------- scratch (device globals; no allocation allowed) ----------
__device__ float4 g_pos4[NB];          // (x,y,z,sq)
__device__ float2 g_Whp[NB * 32];      // packed: [row][lane] = (Wh[l], Wh[l+32])
__device__ float  g_f1[NB];
__device__ float  g_f2[NB];
__device__ float  g_base[NB * FDIM];   // relu(pos@Wp + bp)

__device__ __forceinline__ unsigned int fkey(float f) {
    unsigned int u = __float_as_uint(f);
    return u ^ (0x80000000u | (unsigned int)((int)u >> 31));
}
__device__ __forceinline__ unsigned long long ullmin2(unsigned long long a,
                                                      unsigned long long b) {
    return a < b ? a : b;
}

// ---------------- kernel A: per-node prep (4 rows / 256-thread block) ------
__global__ void __launch_bounds__(256)
prep_kernel(const float* __restrict__ x,
            const float* __restrict__ pos,
            const float* __restrict__ W,
            const float* __restrict__ a,
            const float* __restrict__ Wp,
            const float* __restrict__ bp) {
    int t   = threadIdx.x;
    int r   = t >> 6;            // row slot 0..3
    int j   = t & 63;            // feature 0..63
    int row = blockIdx.x * 4 + r;
    __shared__ float xs[4][FDIM];
    __shared__ float red[4][4];

    xs[r][j] = x[row * FDIM + j];
    __syncthreads();

    float acc = 0.f;
#pragma unroll 16
    for (int i = 0; i < FDIM; i++)
        acc += xs[r][i] * W[i * FDIM + j];
    // packed Wh: float2 element (Wh[j&31].x for j<32, .y for j>=32)
    {
        float* wp = (float*)&g_Whp[row * 32 + (j & 31)];
        wp[j >> 5] = acc;
    }

    float p1 = acc * a[j];
    float p2 = acc * a[FDIM + j];
#pragma unroll
    for (int off = 16; off; off >>= 1) {
        p1 += __shfl_down_sync(0xffffffffu, p1, off);
        p2 += __shfl_down_sync(0xffffffffu, p2, off);
    }
    int lane = j & 31, half = j >> 5;
    if (lane == 0) { red[r][half] = p1; red[r][2 + half] = p2; }

    float px = pos[row * 3 + 0];
    float py = pos[row * 3 + 1];
    float pz = pos[row * 3 + 2];
    float bj = px * Wp[j] + py * Wp[FDIM + j] + pz * Wp[2 * FDIM + j] + bp[j];
    g_base[row * FDIM + j] = bj > 0.f ? bj : 0.f;

    __syncthreads();
    if (j == 0) {
        g_f1[row] = red[r][0] + red[r][1];
        g_f2[row] = red[r][2] + red[r][3];
        float sq  = px * px + py * py + pz * pz;
        g_pos4[row] = make_float4(px, py, pz, sq);
    }
}

// branchless stable float-key insert level (ck/ci become the ejected value)
#define INS_LEVF(kk, ii, ck, ci)                          \
    {                                                     \
        bool c = ck < kk;                                 \
        float nk = c ? ck : kk;                           \
        unsigned int ni = c ? ci : ii;                    \
        ck = c ? kk : ck;  ci = c ? ii : ci;              \
        kk = nk;  ii = ni;                                \
    }
// branchless stable u32-key insert level (refill rescan)
#define INS_LEVU(kk, ii, ck, ci)                          \
    {                                                     \
        bool c = ck < kk;                                 \
        unsigned int nk = c ? ck : kk, ni = c ? ci : ii;  \
        ck = c ? kk : ck;  ci = c ? ii : ci;              \
        kk = nk;  ii = ni;                                \
    }

// packed element: key<<13 | idx<<1 | flag  (flag=1 only on sentinels)
__device__ __forceinline__ unsigned long long pack_e(unsigned int key,
                                                     unsigned int idx) {
    return (((unsigned long long)key) << 13) | (idx << 1);
}

// ---------------- kernel B: warp-per-query kNN(21) + attention -------------
// Lane owns two streams of 64 candidates (m = lane+32i, i<64 / i>=64), each
// kept as exact sorted top-3 (with idx) + exact 4th-key sentinel bound.
// Selection key = pos.w - 2*dot (sq_n dropped: constant per query).
__global__ void __launch_bounds__(TPB, 12)
knn_attn_kernel(float* __restrict__ out) {
    const unsigned FULL = 0xffffffffu;
    int lane = threadIdx.x & 31;
    int wid  = threadIdx.x >> 5;
    int row  = blockIdx.x * (TPB / 32) + wid;      // this warp's query
    int browbase = (row >> 12) << 12;              // first row of batch
    const float4* pb = g_pos4 + browbase;

    float4 q = g_pos4[row];

    // ---- phase 1: two streams, top-3 (+4th-key bound) each ----------------
    const float INF = __int_as_float(0x7f800000);
    float fa0 = INF, fa1 = INF, fa2 = INF, fa3 = INF;
    float fb0 = INF, fb1 = INF, fb2 = INF, fb3 = INF;
    unsigned int ia0 = 0xFFFu, ia1 = 0xFFFu, ia2 = 0xFFFu;
    unsigned int ib0 = 0xFFFu, ib1 = 0xFFFu, ib2 = 0xFFFu;
#pragma unroll 4
    for (int i = 0; i < 64; i++) {
        int mA = lane + 32 * i;
        int mB = mA + 2048;
        float4 pA = pb[mA];
        float4 pB = pb[mB];

        float dA = fmaf(-2.f, fmaf(q.z, pA.z, fmaf(q.y, pA.y, q.x * pA.x)),
                        pA.w);
        unsigned int xiA = (unsigned int)mA;
        INS_LEVF(fa0, ia0, dA, xiA)
        INS_LEVF(fa1, ia1, dA, xiA)
        INS_LEVF(fa2, ia2, dA, xiA)
        fa3 = fminf(fa3, dA);                      // dA now = ejected value

        float dB = fmaf(-2.f, fmaf(q.z, pB.z, fmaf(q.y, pB.y, q.x * pB.x)),
                        pB.w);
        unsigned int xiB = (unsigned int)mB;
        INS_LEVF(fb0, ib0, dB, xiB)
        INS_LEVF(fb1, ib1, dB, xiB)
        INS_LEVF(fb2, ib2, dB, xiB)
        fb3 = fminf(fb3, dB);
    }

    // ---- pack lists; sentinel = exact 4th key, idx-bits 0, flag bit0 ------
    unsigned long long LA1 = pack_e(fkey(fa1), ia1);
    unsigned long long LA2 = pack_e(fkey(fa2), ia2);
    unsigned long long LB1 = pack_e(fkey(fb1), ib1);
    unsigned long long LB2 = pack_e(fkey(fb2), ib2);
    unsigned long long sentA = (((unsigned long long)fkey(fa3)) << 13) | 1ull;
    unsigned long long sentB = (((unsigned long long)fkey(fb3)) << 13) | 1ull;
    unsigned long long headA = pack_e(fkey(fa0), ia0);
    unsigned long long headB = pack_e(fkey(fb0), ib0);
    int apos = 0, bpos = 0;

    // ---- 21 merge rounds; sentinel win -> single-lane stream refill -------
    unsigned int nbr = 0;
    int r = 0;
    while (r < KSEL) {
        unsigned long long h = ullmin2(headA, headB);
        unsigned int hk = (unsigned int)(h >> 13);
        unsigned int w  = __reduce_min_sync(FULL, hk);
        unsigned int cand = (hk == w) ? ((unsigned int)(h >> 1) & 0xFFFu)
                                      : 0xFFFFu;
        unsigned int m = __reduce_min_sync(FULL, cand);
        bool mine = (hk == w) && (((unsigned int)(h >> 1) & 0xFFFu) == m);
        bool sfire = mine && ((unsigned int)h & 1u);
        if (__ballot_sync(FULL, sfire)) {
            if (sfire) {
                // refill the stream whose sentinel fired: top-3 + 4th-key
                // bound among candidates with packed key strictly > cut
                bool fromA = (h == headA);
                unsigned long long cut = fromA ? LA2 : LB2;
                int mbase = fromA ? 0 : 2048;
                unsigned int k0 = ~0u, k1 = ~0u, k2 = ~0u, k3 = ~0u;
                unsigned int i0 = 0xFFFu, i1 = 0xFFFu, i2 = 0xFFFu;
#pragma unroll 1
                for (int i = 0; i < 64; i++) {
                    int mm = lane + 32 * i + mbase;
                    float4 p = pb[mm];
                    float d2 = fmaf(-2.f,
                                    fmaf(q.z, p.z, fmaf(q.y, p.y, q.x * p.x)),
                                    p.w);
                    unsigned int key = fkey(d2);
                    bool ok = pack_e(key, (unsigned int)mm) > cut;
                    unsigned int ck = ok ? key : 0xFFFFFFFFu;
                    unsigned int ci = ok ? (unsigned int)mm : 0xFFFu;
                    INS_LEVU(k0, i0, ck, ci)
                    INS_LEVU(k1, i1, ck, ci)
                    INS_LEVU(k2, i2, ck, ci)
                    k3 = min(k3, ck);              // ck = ejected value
                }
                unsigned long long nh = pack_e(k0, i0);
                unsigned long long n1 = pack_e(k1, i1);
                unsigned long long n2 = pack_e(k2, i2);
                unsigned long long ns = (((unsigned long long)k3) << 13) | 1ull;
                if (fromA) { headA = nh; LA1 = n1; LA2 = n2; sentA = ns;
                             apos = 0; }
                else       { headB = nh; LB1 = n1; LB2 = n2; sentB = ns;
                             bpos = 0; }
            }
            continue;                    // retry this round
        }
        if (lane == r - 1) nbr = m;      // rounds 1..20 record neighbors
        if (mine) {
            if (h == headA) {
                apos++;
                headA = (apos == 1) ? LA1 : (apos == 2) ? LA2 : sentA;
            } else {
                bpos++;
                headB = (bpos == 1) ? LB1 : (bpos == 2) ? LB2 : sentB;
            }
        }
        r++;
    }

    // ---- softmax over the 20 neighbors (in-warp) --------------------------
    float e = -1e30f;
    if (lane < KSEL - 1) {
        float val = g_f1[row] + g_f2[browbase + (int)nbr];
        e = val > 0.f ? val : 0.2f * val;            // leaky relu 0.2
    }
    float mx = e;
#pragma unroll
    for (int off = 16; off; off >>= 1)
        mx = fmaxf(mx, __shfl_xor_sync(FULL, mx, off));
    float ex = (lane < KSEL - 1) ? expf(e - mx) : 0.f;
    float sm = ex;
#pragma unroll
    for (int off = 16; off; off >>= 1)
        sm += __shfl_xor_sync(FULL, sm, off);
    float attn = ex / sm;                            // valid on lanes < 20

    // ---- weighted Wh gather + base + elu (2 features per lane) ------------
    float acc0 = g_base[row * FDIM + lane];
    float acc1 = g_base[row * FDIM + 32 + lane];
#pragma unroll
    for (int j = 0; j < KSEL - 1; j++) {
        int   mj = (int)__shfl_sync(FULL, nbr, j);
        float aj = __shfl_sync(FULL, attn, j);
        float2 wv = g_Whp[(browbase + mj) * 32 + lane];
        acc0 = fmaf(aj, wv.x, acc0);
        acc1 = fmaf(aj, wv.y, acc1);
    }
    out[row * FDIM + lane]      = acc0 > 0.f ? acc0 : expm1f(acc0);
    out[row * FDIM + 32 + lane] = acc1 > 0.f ? acc1 : expm1f(acc1);
}

// ---------------- launch ----------------------------------------------------
extern "C" void kernel_launch(void* const* d_in, const int* in_sizes, int n_in,
                              void* d_out, int out_size) {
    (void)in_sizes; (void)n_in; (void)out_size;
    const float* x   = (const float*)d_in[0];
    const float* pos = (const float*)d_in[1];
    const float* W   = (const float*)d_in[2];
    const float* a   = (const float*)d_in[3];
    const float* Wp  = (const float*)d_in[4];
    const float* bp  = (const float*)d_in[5];
    float* out = (float*)d_out;

    prep_kernel<<<NB / 4, 256>>>(x, pos, W, a, Wp, bp);
    knn_attn_kernel<<<NB / (TPB / 32), TPB>>>(out);
}